// round 4
// baseline (speedup 1.0000x reference)
#include <cuda_runtime.h>
#include <math.h>

#define BSZ  8
#define KPS  8
#define NPK  16
#define TT   3072
#define WGW  64
#define HHH  256
#define WCC  256
#define RHH  1024
#define RWW  512
#define MM   64          // BSZ*KPS

#define C1H 1024
#define C1W 31
#define C2H 341
#define C2W 15
#define C3H 113
#define C3W 7

#define N1  (MM*C1H*C1W)     // 2031616
#define N2  (MM*C2H*C2W)     // 327360 (per channel)
#define N3  (MM*C3H*C3W)     // 50624
#define NF  (BSZ*RHH*RWW)    // 4194304
#define NG  (BSZ*KPS*TT*WGW) // 12582912

// ---------------- scratch (device globals; no allocation) ----------------
__device__ unsigned int g_maxbits;
__device__ double g_s1, g_q1;
__device__ double g_s2[2], g_q2[2];
__device__ double g_s3, g_q3;
__device__ double g_sf, g_qf;

__device__ float g_conv1[N1];
__device__ float g_act1[N1];
__device__ float g_conv2[2*N2];
__device__ float g_conv3[N3];
__device__ float g_rowval[MM*C3H];
__device__ float g_genr[MM*RHH];
__device__ int   g_vint[MM*HHH];
__device__ float g_mix[NF];
__device__ float g_yraw[NF];

// ---------------- helpers ----------------
__device__ __forceinline__ float lrelu(float x){ return x >= 0.f ? x : 0.1f*x; }

__device__ __forceinline__ double warpSumD(double v){
#pragma unroll
    for (int o = 16; o > 0; o >>= 1) v += __shfl_down_sync(0xffffffffu, v, o);
    return v;
}
__device__ __forceinline__ float warpMaxF(float v){
#pragma unroll
    for (int o = 16; o > 0; o >>= 1) v = fmaxf(v, __shfl_down_sync(0xffffffffu, v, o));
    return v;
}

// block (256 threads) reduce two doubles -> atomicAdd to globals
__device__ __forceinline__ void blockAtomicAdd2(double a, double b, double* da, double* db){
    a = warpSumD(a); b = warpSumD(b);
    __shared__ double sa[8], sb[8];
    int lane = threadIdx.x & 31, w = threadIdx.x >> 5;
    if (lane == 0){ sa[w] = a; sb[w] = b; }
    __syncthreads();
    if (w == 0){
        a = (lane < 8) ? sa[lane] : 0.0;
        b = (lane < 8) ? sb[lane] : 0.0;
        a = warpSumD(a); b = warpSumD(b);
        if (lane == 0){ atomicAdd(da, a); atomicAdd(db, b); }
    }
}

// ---------------- kernels ----------------
__global__ void k_init(){
    g_maxbits = 0u;
    g_s1 = 0; g_q1 = 0;
    g_s2[0] = 0; g_s2[1] = 0; g_q2[0] = 0; g_q2[1] = 0;
    g_s3 = 0; g_q3 = 0;
    g_sf = 0; g_qf = 0;
}

__global__ void __launch_bounds__(256) k_maxabs(const float4* __restrict__ g, int n4){
    float m = 0.f;
    for (int i = blockIdx.x*blockDim.x + threadIdx.x; i < n4; i += gridDim.x*blockDim.x){
        float4 v = g[i];
        m = fmaxf(m, fmaxf(fmaxf(fabsf(v.x), fabsf(v.y)), fmaxf(fabsf(v.z), fabsf(v.w))));
    }
    m = warpMaxF(m);
    __shared__ float sm[8];
    int lane = threadIdx.x & 31, w = threadIdx.x >> 5;
    if (lane == 0) sm[w] = m;
    __syncthreads();
    if (w == 0){
        m = (lane < 8) ? sm[lane] : 0.f;
        m = warpMaxF(m);
        if (lane == 0) atomicMax(&g_maxbits, __float_as_uint(m));
    }
}

__global__ void __launch_bounds__(256) k_conv1(const float* __restrict__ g,
                                               const float* __restrict__ w1,
                                               const float* __restrict__ b1){
    int idx = blockIdx.x*blockDim.x + threadIdx.x;
    double s = 0.0, q = 0.0;
    if (idx < N1){
        int j = idx % C1W; int t = idx / C1W; int i = t % C1H; int m = t / C1H;
        float inv = 1.f / __uint_as_float(g_maxbits);
        const float* base = g + (size_t)m*(TT*WGW) + (3*i)*WGW + 2*j;
        float acc = 0.f;
#pragma unroll
        for (int p = 0; p < 3; p++){
            const float* r = base + p*WGW;
            acc += w1[p*3+0]*r[0] + w1[p*3+1]*r[1] + w1[p*3+2]*r[2];
        }
        float y = acc*inv + b1[0];
        g_conv1[idx] = y;
        s = (double)y; q = (double)y*(double)y;
    }
    blockAtomicAdd2(s, q, &g_s1, &g_q1);
}

__global__ void __launch_bounds__(256) k_act1(const float* __restrict__ g1p,
                                              const float* __restrict__ be1p){
    int idx = blockIdx.x*blockDim.x + threadIdx.x;
    if (idx >= N1) return;
    double mean = g_s1 / (double)N1;
    double var  = g_q1 / (double)N1 - mean*mean;
    float istd = (float)(1.0 / sqrt(var + 1e-5));
    float mf = (float)mean;
    float y = g_conv1[idx];
    g_act1[idx] = lrelu((y - mf)*istd*g1p[0] + be1p[0]);
}

__global__ void __launch_bounds__(256) k_conv2(const float* __restrict__ w2,
                                               const float* __restrict__ b2){
    int idx = blockIdx.x*blockDim.x + threadIdx.x;
    double s0 = 0, q0 = 0, s1 = 0, q1 = 0;
    if (idx < N2){
        int j = idx % C2W; int t = idx / C2W; int i = t % C2H; int m = t / C2H;
        const float* A = g_act1 + m*(C1H*C1W);
        int r0 = 3*i - 2, c0 = 2*j - 2;
        float a[7][7];
#pragma unroll
        for (int r = 0; r < 7; r++){
            int rr = r0 + r;
            bool rok = (rr >= 0 && rr < C1H);
#pragma unroll
            for (int c = 0; c < 7; c++){
                int cc = c0 + c;
                a[r][c] = (rok && cc >= 0 && cc < C1W) ? A[rr*C1W + cc] : -1e30f;
            }
        }
        float o0 = b2[0], o1 = b2[1];
#pragma unroll
        for (int p = 0; p < 3; p++){
#pragma unroll
            for (int qq = 0; qq < 3; qq++){
                float v0 = a[p+2][qq+2];
                float m3 = -1e30f, m5 = -1e30f;
#pragma unroll
                for (int dr = 0; dr < 3; dr++)
#pragma unroll
                    for (int dc = 0; dc < 3; dc++)
                        m3 = fmaxf(m3, a[p+1+dr][qq+1+dc]);
#pragma unroll
                for (int dr = 0; dr < 5; dr++)
#pragma unroll
                    for (int dc = 0; dc < 5; dc++)
                        m5 = fmaxf(m5, a[p+dr][qq+dc]);
                int off = p*3 + qq;
                o0 += w2[off]*v0      + w2[9+off]*m3      + w2[18+off]*m5;
                o1 += w2[27+off]*v0   + w2[36+off]*m3     + w2[45+off]*m5;
            }
        }
        g_conv2[((m*2+0)*C2H + i)*C2W + j] = o0;
        g_conv2[((m*2+1)*C2H + i)*C2W + j] = o1;
        s0 = o0; q0 = (double)o0*(double)o0;
        s1 = o1; q1 = (double)o1*(double)o1;
    }
    blockAtomicAdd2(s0, q0, &g_s2[0], &g_q2[0]);
    blockAtomicAdd2(s1, q1, &g_s2[1], &g_q2[1]);
}

__global__ void __launch_bounds__(256) k_conv3(const float* __restrict__ w3,
                                               const float* __restrict__ b3,
                                               const float* __restrict__ g2p,
                                               const float* __restrict__ be2p){
    int idx = blockIdx.x*blockDim.x + threadIdx.x;
    double s = 0, q = 0;
    if (idx < N3){
        int j = idx % C3W; int t = idx / C3W; int i = t % C3H; int m = t / C3H;
        float mean[2], sc[2], sh[2];
#pragma unroll
        for (int c = 0; c < 2; c++){
            double mn = g_s2[c] / (double)N2;
            double vr = g_q2[c] / (double)N2 - mn*mn;
            mean[c] = (float)mn;
            sc[c] = (float)(1.0 / sqrt(vr + 1e-5)) * g2p[c];
            sh[c] = be2p[c];
        }
        float acc = b3[0];
#pragma unroll
        for (int c = 0; c < 2; c++){
            const float* B = g_conv2 + ((m*2+c)*C2H)*C2W;
#pragma unroll
            for (int p = 0; p < 3; p++){
#pragma unroll
                for (int qq = 0; qq < 2; qq++){
                    float raw = B[(3*i+p)*C2W + 2*j+qq];
                    float act = lrelu((raw - mean[c])*sc[c] + sh[c]);
                    acc += w3[c*6 + p*2 + qq]*act;
                }
            }
        }
        g_conv3[idx] = acc;
        s = (double)acc; q = (double)acc*(double)acc;
    }
    blockAtomicAdd2(s, q, &g_s3, &g_q3);
}

__global__ void __launch_bounds__(256) k_rowval(const float* __restrict__ g3p,
                                                const float* __restrict__ be3p){
    int idx = blockIdx.x*blockDim.x + threadIdx.x;
    if (idx >= MM*C3H) return;
    int h = idx % C3H; int m = idx / C3H;
    double mn = g_s3 / (double)N3;
    double vr = g_q3 / (double)N3 - mn*mn;
    float mf = (float)mn;
    float sc = (float)(1.0 / sqrt(vr + 1e-5)) * g3p[0];
    float sh = be3p[0];
    const float wcol[7] = {4.f/37.f, 5.f/37.f, 6.f/37.f, 7.f/37.f, 6.f/37.f, 5.f/37.f, 4.f/37.f};
    const float* B = g_conv3 + (m*C3H + h)*C3W;
    float rv = 0.f;
#pragma unroll
    for (int j = 0; j < 7; j++)
        rv += wcol[j] * lrelu((B[j] - mf)*sc + sh);
    g_rowval[idx] = rv;
}

__global__ void __launch_bounds__(256) k_genr(){
    int idx = blockIdx.x*blockDim.x + threadIdx.x;
    if (idx >= MM*RHH) return;
    int rh = idx % RHH; int m = idx / RHH;
    float ih = (rh + 0.5f)*(113.0f/1024.0f) - 0.5f;
    ih = fminf(fmaxf(ih, 0.f), 112.f);
    int h0 = (int)ih; float f = ih - (float)h0;
    int h1 = min(h0 + 1, 112);
    const float* R = g_rowval + m*C3H;
    g_genr[idx] = (1.f - f)*R[h0] + f*R[h1];
}

__global__ void __launch_bounds__(256) k_vint(const float* __restrict__ cv,
                                              const float* __restrict__ VMM){
    int idx = blockIdx.x*blockDim.x + threadIdx.x;
    if (idx >= MM*HHH) return;
    int h = idx % HHH; int m = idx / HHH; int b = m / KPS;
    const float* C = cv + m*NPK*2;
    const float dt = 7000.0f/255.0f;
    float vm0 = VMM[b*2];
    float dv = (VMM[b*2+1] - vm0)/255.0f;
    float tq = (float)h;
    float tp = C[0]/dt, vp = (C[1] - vm0)/dv;
    float val;
    if (tq <= tp){
        val = vp;
    } else {
        val = (C[2*(NPK-1)+1] - vm0)/dv;  // right endpoint default
        for (int n = 1; n < NPK; n++){
            float tn = C[2*n]/dt, vn = (C[2*n+1] - vm0)/dv;
            if (tq <= tn){ val = vp + (vn - vp)*(tq - tp)/(tn - tp); break; }
            tp = tn; vp = vn;
        }
    }
    int vi = (int)val;                 // truncation toward zero, matches astype(int32)
    vi = min(WCC-1, max(0, vi));
    g_vint[idx] = vi;
}

__global__ void __launch_bounds__(256) k_mix(){
    int idx = blockIdx.x*blockDim.x + threadIdx.x;
    if (idx >= NF) return;
    int rw = idx % RWW; int t = idx / RWW; int rh = t % RHH; int b = t / RHH;
    float ih = (rh + 0.5f)*0.25f - 0.5f;
    ih = fminf(fmaxf(ih, 0.f), 255.f);
    int h0 = (int)ih; float fh = ih - (float)h0; int h1 = min(h0 + 1, 255);
    float iw = (rw + 0.5f)*0.5f - 0.5f;
    iw = fminf(fmaxf(iw, 0.f), 255.f);
    int c0 = (int)iw; float fw = iw - (float)c0; int c1 = min(c0 + 1, 255);
    float acc = 0.f;
#pragma unroll
    for (int k = 0; k < KPS; k++){
        int m = b*KPS + k;
        float g = g_genr[m*RHH + rh];
        int v0 = g_vint[m*HHH + h0];
        int v1 = g_vint[m*HHH + h1];
        float s0 = (c0 == v0 ? 1.f - fw : 0.f) + (c1 == v0 ? fw : 0.f);
        float s1 = (c0 == v1 ? 1.f - fw : 0.f) + (c1 == v1 ? fw : 0.f);
        float mv = 0.01f + 0.9f*((1.f - fh)*s0 + fh*s1);
        acc += g*mv;
    }
    g_mix[idx] = acc;
}

__global__ void __launch_bounds__(256) k_convf(const float* __restrict__ wf,
                                               const float* __restrict__ bf){
    int idx = blockIdx.x*blockDim.x + threadIdx.x;
    double s = 0, q = 0;
    if (idx < NF){
        int rw = idx % RWW; int t = idx / RWW; int rh = t % RHH; int b = t / RHH;
        float acc = bf[0];
        const float* Mx = g_mix + (size_t)b*RHH*RWW;
#pragma unroll
        for (int p = 0; p < 3; p++){
            int r = rh - 1 + p;
            if (r < 0 || r >= RHH) continue;
#pragma unroll
            for (int qq = 0; qq < 3; qq++){
                int c = rw - 1 + qq;
                if (c < 0 || c >= RWW) continue;
                acc += wf[p*3+qq]*Mx[r*RWW + c];
            }
        }
        g_yraw[idx] = acc;
        s = (double)acc; q = (double)acc*(double)acc;
    }
    blockAtomicAdd2(s, q, &g_sf, &g_qf);
}

__global__ void __launch_bounds__(256) k_final(const float* __restrict__ gfp,
                                               const float* __restrict__ befp,
                                               float* __restrict__ out){
    int idx = blockIdx.x*blockDim.x + threadIdx.x;
    if (idx >= NF) return;
    double mn = g_sf / (double)NF;
    double vr = g_qf / (double)NF - mn*mn;
    float mf = (float)mn;
    float sc = (float)(1.0 / sqrt(vr + 1e-5)) * gfp[0];
    float sh = befp[0];
    out[idx] = lrelu((g_yraw[idx] - mf)*sc + sh);
}

// ---------------- launch ----------------
extern "C" void kernel_launch(void* const* d_in, const int* in_sizes, int n_in,
                              void* d_out, int out_size){
    const float* gather = (const float*)d_in[0];
    const float* cv     = (const float*)d_in[1];
    const float* VMM    = (const float*)d_in[2];
    const float* w1  = (const float*)d_in[3];
    const float* b1  = (const float*)d_in[4];
    const float* g1  = (const float*)d_in[5];
    const float* be1 = (const float*)d_in[6];
    const float* w2  = (const float*)d_in[7];
    const float* b2  = (const float*)d_in[8];
    const float* g2  = (const float*)d_in[9];
    const float* be2 = (const float*)d_in[10];
    const float* w3  = (const float*)d_in[11];
    const float* b3  = (const float*)d_in[12];
    const float* g3  = (const float*)d_in[13];
    const float* be3 = (const float*)d_in[14];
    const float* wf  = (const float*)d_in[15];
    const float* bf  = (const float*)d_in[16];
    const float* gf  = (const float*)d_in[17];
    const float* bef = (const float*)d_in[18];
    float* out = (float*)d_out;

    k_init<<<1, 1>>>();
    k_maxabs<<<1024, 256>>>((const float4*)gather, NG/4);
    k_conv1<<<(N1 + 255)/256, 256>>>(gather, w1, b1);
    k_act1<<<(N1 + 255)/256, 256>>>(g1, be1);
    k_conv2<<<(N2 + 255)/256, 256>>>(w2, b2);
    k_conv3<<<(N3 + 255)/256, 256>>>(w3, b3, g2, be2);
    k_rowval<<<(MM*C3H + 255)/256, 256>>>(g3, be3);
    k_vint<<<(MM*HHH + 255)/256, 256>>>(cv, VMM);
    k_genr<<<(MM*RHH + 255)/256, 256>>>();
    k_mix<<<(NF + 255)/256, 256>>>();
    k_convf<<<(NF + 255)/256, 256>>>(wf, bf);
    k_final<<<(NF + 255)/256, 256>>>(gf, bef, out);
}

// round 5
// speedup vs baseline: 2.7474x; 2.7474x over previous
#include <cuda_runtime.h>
#include <math.h>

#define BSZ  8
#define KPS  8
#define NPK  16
#define TT   3072
#define WGW  64
#define HHH  256
#define WCC  256
#define RHH  1024
#define RWW  512
#define MM   64          // BSZ*KPS

#define C1H 1024
#define C1W 31
#define C2H 341
#define C2W 15
#define C3H 113
#define C3W 7

#define N1  (MM*C1H*C1W)     // 2031616
#define N2  (MM*C2H*C2W)     // 327360 per channel
#define N3  (MM*C3H*C3W)     // 50624
#define NF  (BSZ*RHH*RWW)    // 4194304

#define TROWS 16             // output rows per tile in the final stage

// ---------------- scratch (device globals; no allocation) ----------------
__device__ unsigned int g_maxbits;
__device__ double g_s1, g_q1;
__device__ double g_s2[2], g_q2[2];
__device__ double g_s3, g_q3;
__device__ double g_sf, g_qf;

// precomputed BN affine params (float)
__device__ float g_A1, g_B1;
__device__ float g_A2[2], g_B2[2];
__device__ float g_A3, g_B3;
__device__ float g_sF, g_hF;

__device__ float g_conv1[N1];        // RAW conv1 (no norm, no BN)
__device__ float g_conv2[2*N2];      // RAW conv2
__device__ float g_conv3[N3];        // RAW conv3
__device__ float g_rowval[MM*C3H];
__device__ float g_genr[MM*RHH];
__device__ int   g_vint[MM*HHH];

// ---------------- helpers ----------------
__device__ __forceinline__ float lrelu(float x){ return x >= 0.f ? x : 0.1f*x; }

__device__ __forceinline__ float warpSumF(float v){
#pragma unroll
    for (int o = 16; o > 0; o >>= 1) v += __shfl_down_sync(0xffffffffu, v, o);
    return v;
}
__device__ __forceinline__ float warpMaxF(float v){
#pragma unroll
    for (int o = 16; o > 0; o >>= 1) v = fmaxf(v, __shfl_down_sync(0xffffffffu, v, o));
    return v;
}

// 256-thread block: reduce (a,b) floats, accumulate as double into globals.
// FP64 ops: ~16 per block (vs ~10 per thread before).
__device__ __forceinline__ void blockRedAdd2(float a, float b, double* da, double* db){
    a = warpSumF(a); b = warpSumF(b);
    __shared__ double sa[8], sb[8];
    int lane = threadIdx.x & 31, w = threadIdx.x >> 5;
    if (lane == 0){ sa[w] = (double)a; sb[w] = (double)b; }
    __syncthreads();
    if (w == 0){
        double x = (lane < 8) ? sa[lane] : 0.0;
        double y = (lane < 8) ? sb[lane] : 0.0;
#pragma unroll
        for (int o = 4; o > 0; o >>= 1){
            x += __shfl_down_sync(0xffffffffu, x, o);
            y += __shfl_down_sync(0xffffffffu, y, o);
        }
        if (lane == 0){ atomicAdd(da, x); atomicAdd(db, y); }
    }
}

// ---------------- kernels ----------------
__global__ void k_init(){
    g_maxbits = 0u;
    g_s1 = 0; g_q1 = 0;
    g_s2[0] = 0; g_s2[1] = 0; g_q2[0] = 0; g_q2[1] = 0;
    g_s3 = 0; g_q3 = 0;
    g_sf = 0; g_qf = 0;
}

// conv1 RAW (no 1/max, no bias — both absorbed into BN1 affine) + maxabs + stats
__global__ void __launch_bounds__(256) k_conv1(const float* __restrict__ g,
                                               const float* __restrict__ w1){
    int idx = blockIdx.x*blockDim.x + threadIdx.x;
    float s = 0.f, q = 0.f, mx = 0.f;
    if (idx < N1){
        int j = idx % C1W; int t = idx / C1W; int i = t % C1H; int m = t / C1H;
        const float* base = g + (size_t)m*(TT*WGW) + (3*i)*WGW + 2*j;
        float w[9];
#pragma unroll
        for (int p = 0; p < 9; p++) w[p] = __ldg(&w1[p]);
        float acc = 0.f;
#pragma unroll
        for (int p = 0; p < 3; p++){
            const float* r = base + p*WGW;
            float a = r[0], bb = r[1], c = r[2];
            acc += w[p*3+0]*a + w[p*3+1]*bb + w[p*3+2]*c;
            mx = fmaxf(mx, fmaxf(fmaxf(fabsf(a), fabsf(bb)), fabsf(c)));
            if (j == C1W-1) mx = fmaxf(mx, fabsf(r[3]));   // col 63 coverage
        }
        g_conv1[idx] = acc;
        s = acc; q = acc*acc;
    }
    // block max -> atomicMax (positive float bits are order-preserving)
    {
        float m = warpMaxF(mx);
        __shared__ float sm[8];
        int lane = threadIdx.x & 31, w = threadIdx.x >> 5;
        if (lane == 0) sm[w] = m;
        __syncthreads();
        if (w == 0){
            m = (lane < 8) ? sm[lane] : 0.f;
            m = warpMaxF(m);
            if (lane == 0) atomicMax(&g_maxbits, __float_as_uint(m));
        }
        __syncthreads();
    }
    blockRedAdd2(s, q, &g_s1, &g_q1);
}

// BN1 affine from RAW stats: y = c*inv + b1; BN cancels b1; A = inv*istd*g1
__global__ void k_fin1(const float* __restrict__ g1, const float* __restrict__ be1){
    double inv  = 1.0 / (double)__uint_as_float(g_maxbits);
    double mc   = g_s1 / (double)N1;
    double varc = g_q1 / (double)N1 - mc*mc;
    double istd = 1.0 / sqrt(inv*inv*varc + 1e-5);
    double A = inv*istd*(double)g1[0];
    g_A1 = (float)A;
    g_B1 = (float)((double)be1[0] - A*mc);
}

__global__ void __launch_bounds__(256) k_conv2(const float* __restrict__ w2,
                                               const float* __restrict__ b2){
    int idx = blockIdx.x*blockDim.x + threadIdx.x;
    float s0 = 0, q0 = 0, s1 = 0, q1 = 0;
    if (idx < N2){
        int j = idx % C2W; int t = idx / C2W; int i = t % C2H; int m = t / C2H;
        const float* A = g_conv1 + m*(C1H*C1W);
        float A1 = g_A1, B1 = g_B1;
        int r0 = 3*i - 2, c0 = 2*j - 2;
        float a[7][7];
#pragma unroll
        for (int r = 0; r < 7; r++){
            int rr = r0 + r;
            bool rok = (rr >= 0 && rr < C1H);
#pragma unroll
            for (int c = 0; c < 7; c++){
                int cc = c0 + c;
                a[r][c] = (rok && cc >= 0 && cc < C1W)
                          ? lrelu(A[rr*C1W + cc]*A1 + B1) : -1e30f;
            }
        }
        float o0 = b2[0], o1 = b2[1];
#pragma unroll
        for (int p = 0; p < 3; p++){
#pragma unroll
            for (int qq = 0; qq < 3; qq++){
                float v0 = a[p+2][qq+2];
                float m3 = -1e30f, m5 = -1e30f;
#pragma unroll
                for (int dr = 0; dr < 3; dr++)
#pragma unroll
                    for (int dc = 0; dc < 3; dc++)
                        m3 = fmaxf(m3, a[p+1+dr][qq+1+dc]);
#pragma unroll
                for (int dr = 0; dr < 5; dr++)
#pragma unroll
                    for (int dc = 0; dc < 5; dc++)
                        m5 = fmaxf(m5, a[p+dr][qq+dc]);
                int off = p*3 + qq;
                o0 += w2[off]*v0      + w2[9+off]*m3      + w2[18+off]*m5;
                o1 += w2[27+off]*v0   + w2[36+off]*m3     + w2[45+off]*m5;
            }
        }
        g_conv2[((m*2+0)*C2H + i)*C2W + j] = o0;
        g_conv2[((m*2+1)*C2H + i)*C2W + j] = o1;
        s0 = o0; q0 = o0*o0;
        s1 = o1; q1 = o1*o1;
    }
    blockRedAdd2(s0, q0, &g_s2[0], &g_q2[0]);
    blockRedAdd2(s1, q1, &g_s2[1], &g_q2[1]);
}

__global__ void k_fin2(const float* __restrict__ g2, const float* __restrict__ be2){
#pragma unroll
    for (int c = 0; c < 2; c++){
        double mn = g_s2[c] / (double)N2;
        double vr = g_q2[c] / (double)N2 - mn*mn;
        double sc = (double)g2[c] / sqrt(vr + 1e-5);
        g_A2[c] = (float)sc;
        g_B2[c] = (float)((double)be2[c] - mn*sc);
    }
}

__global__ void __launch_bounds__(256) k_conv3(const float* __restrict__ w3,
                                               const float* __restrict__ b3){
    int idx = blockIdx.x*blockDim.x + threadIdx.x;
    float s = 0, q = 0;
    if (idx < N3){
        int j = idx % C3W; int t = idx / C3W; int i = t % C3H; int m = t / C3H;
        float acc = b3[0];
#pragma unroll
        for (int c = 0; c < 2; c++){
            float A2 = g_A2[c], B2 = g_B2[c];
            const float* B = g_conv2 + ((m*2+c)*C2H)*C2W;
#pragma unroll
            for (int p = 0; p < 3; p++){
#pragma unroll
                for (int qq = 0; qq < 2; qq++){
                    float raw = B[(3*i+p)*C2W + 2*j+qq];
                    acc += w3[c*6 + p*2 + qq]*lrelu(raw*A2 + B2);
                }
            }
        }
        g_conv3[idx] = acc;
        s = acc; q = acc*acc;
    }
    blockRedAdd2(s, q, &g_s3, &g_q3);
}

__global__ void k_fin3(const float* __restrict__ g3, const float* __restrict__ be3){
    double mn = g_s3 / (double)N3;
    double vr = g_q3 / (double)N3 - mn*mn;
    double sc = (double)g3[0] / sqrt(vr + 1e-5);
    g_A3 = (float)sc;
    g_B3 = (float)((double)be3[0] - mn*sc);
}

__global__ void __launch_bounds__(256) k_rowval(){
    int idx = blockIdx.x*blockDim.x + threadIdx.x;
    if (idx >= MM*C3H) return;
    float A3 = g_A3, B3 = g_B3;
    const float wcol[7] = {4.f/37.f, 5.f/37.f, 6.f/37.f, 7.f/37.f, 6.f/37.f, 5.f/37.f, 4.f/37.f};
    const float* B = g_conv3 + idx*C3W;
    float rv = 0.f;
#pragma unroll
    for (int j = 0; j < 7; j++)
        rv += wcol[j] * lrelu(B[j]*A3 + B3);
    g_rowval[idx] = rv;
}

__global__ void __launch_bounds__(256) k_genr(){
    int idx = blockIdx.x*blockDim.x + threadIdx.x;
    if (idx >= MM*RHH) return;
    int rh = idx % RHH; int m = idx / RHH;
    float ih = (rh + 0.5f)*(113.0f/1024.0f) - 0.5f;
    ih = fminf(fmaxf(ih, 0.f), 112.f);
    int h0 = (int)ih; float f = ih - (float)h0;
    int h1 = min(h0 + 1, 112);
    const float* R = g_rowval + m*C3H;
    g_genr[idx] = (1.f - f)*R[h0] + f*R[h1];
}

__global__ void __launch_bounds__(256) k_vint(const float* __restrict__ cv,
                                              const float* __restrict__ VMM){
    int idx = blockIdx.x*blockDim.x + threadIdx.x;
    if (idx >= MM*HHH) return;
    int h = idx % HHH; int m = idx / HHH; int b = m / KPS;
    const float* C = cv + m*NPK*2;
    const float dt = 7000.0f/255.0f;
    float vm0 = VMM[b*2];
    float dv = (VMM[b*2+1] - vm0)/255.0f;
    float tq = (float)h;
    float tp = C[0]/dt, vp = (C[1] - vm0)/dv;
    float val;
    if (tq <= tp){
        val = vp;
    } else {
        val = (C[2*(NPK-1)+1] - vm0)/dv;
        for (int n = 1; n < NPK; n++){
            float tn = C[2*n]/dt, vn = (C[2*n+1] - vm0)/dv;
            if (tq <= tn){ val = vp + (vn - vp)*(tq - tp)/(tn - tp); break; }
            tp = tn; vp = vn;
        }
    }
    int vi = (int)val;
    vi = min(WCC-1, max(0, vi));
    g_vint[idx] = vi;
}

// -------- fused back half: mix recomputed in smem, conv_f in-tile ---------
// Tile: TROWS output rows x 512 cols per block; TROWS+2 mix rows in smem.
// PASS==0: stats only (no global stores). PASS==1: normalize + write out.
template <int PASS>
__device__ __forceinline__ void tileF(const float* __restrict__ wf,
                                      const float* __restrict__ bf,
                                      float* __restrict__ out){
    __shared__ float s_mix[TROWS+2][RWW];
    __shared__ float s_g[TROWS+2][8];
    __shared__ int   s_v0[TROWS+2][8];
    __shared__ int   s_v1[TROWS+2][8];
    __shared__ float s_fh[TROWS+2];

    int b   = blockIdx.x / (RHH/TROWS);
    int rh0 = (blockIdx.x % (RHH/TROWS)) * TROWS;
    int tid = threadIdx.x;

    if (tid < (TROWS+2)*8){
        int r = tid >> 3, k = tid & 7;
        int gr = rh0 - 1 + r;
        float g = 0.f, fh = 0.f; int v0 = 0, v1 = 0;
        if (gr >= 0 && gr < RHH){
            float ih = (gr + 0.5f)*0.25f - 0.5f;
            ih = fminf(fmaxf(ih, 0.f), 255.f);
            int h0 = (int)ih; fh = ih - (float)h0; int h1 = min(h0 + 1, 255);
            int m = b*KPS + k;
            g  = g_genr[m*RHH + gr];
            v0 = g_vint[m*HHH + h0];
            v1 = g_vint[m*HHH + h1];
        }
        s_g[r][k] = g; s_v0[r][k] = v0; s_v1[r][k] = v1;
        if (k == 0) s_fh[r] = fh;
    }
    __syncthreads();

    // compute mix rows: each thread owns cols tid and tid+256
#pragma unroll
    for (int half = 0; half < 2; half++){
        int c = tid + half*256;
        float iw = (c + 0.5f)*0.5f - 0.5f;
        iw = fminf(fmaxf(iw, 0.f), 255.f);
        int c0 = (int)iw; float fw = iw - (float)c0; int c1 = min(c0 + 1, 255);
        for (int r = 0; r < TROWS+2; r++){
            float fh = s_fh[r];
            float acc = 0.f;
#pragma unroll
            for (int k = 0; k < 8; k++){
                float g = s_g[r][k];
                int v0 = s_v0[r][k], v1 = s_v1[r][k];
                float s0 = (c0 == v0 ? 1.f - fw : 0.f) + (c1 == v0 ? fw : 0.f);
                float s1 = (c0 == v1 ? 1.f - fw : 0.f) + (c1 == v1 ? fw : 0.f);
                acc += g*(0.01f + 0.9f*((1.f - fh)*s0 + fh*s1));
            }
            s_mix[r][c] = acc;
        }
    }
    __syncthreads();

    float W[9];
#pragma unroll
    for (int i = 0; i < 9; i++) W[i] = __ldg(&wf[i]);
    float bb = __ldg(&bf[0]);

    float sc = 0.f, sh = 0.f;
    if (PASS == 1){ sc = g_sF; sh = g_hF; }

    float s = 0.f, q = 0.f;
    for (int orow = 0; orow < TROWS; orow++){
#pragma unroll
        for (int half = 0; half < 2; half++){
            int c = tid + half*256;
            float acc = bb;
#pragma unroll
            for (int p = 0; p < 3; p++){
#pragma unroll
                for (int qq = 0; qq < 3; qq++){
                    int cc = c - 1 + qq;
                    if (cc >= 0 && cc < RWW)
                        acc += W[p*3+qq]*s_mix[orow+p][cc];
                }
            }
            if (PASS == 0){
                s += acc; q += acc*acc;
            } else {
                out[((size_t)b*RHH + rh0 + orow)*RWW + c] = lrelu(acc*sc + sh);
            }
        }
    }
    if (PASS == 0) blockRedAdd2(s, q, &g_sf, &g_qf);
}

__global__ void __launch_bounds__(256) k_statsF(const float* __restrict__ wf,
                                                const float* __restrict__ bf){
    tileF<0>(wf, bf, nullptr);
}

__global__ void k_finF(const float* __restrict__ gf, const float* __restrict__ bef){
    double mn = g_sf / (double)NF;
    double vr = g_qf / (double)NF - mn*mn;
    double sc = (double)gf[0] / sqrt(vr + 1e-5);
    g_sF = (float)sc;
    g_hF = (float)((double)bef[0] - mn*sc);
}

__global__ void __launch_bounds__(256) k_outF(const float* __restrict__ wf,
                                              const float* __restrict__ bf,
                                              float* __restrict__ out){
    tileF<1>(wf, bf, out);
}

// ---------------- launch ----------------
extern "C" void kernel_launch(void* const* d_in, const int* in_sizes, int n_in,
                              void* d_out, int out_size){
    const float* gather = (const float*)d_in[0];
    const float* cv     = (const float*)d_in[1];
    const float* VMM    = (const float*)d_in[2];
    const float* w1  = (const float*)d_in[3];
    const float* g1  = (const float*)d_in[5];
    const float* be1 = (const float*)d_in[6];
    const float* w2  = (const float*)d_in[7];
    const float* b2  = (const float*)d_in[8];
    const float* g2  = (const float*)d_in[9];
    const float* be2 = (const float*)d_in[10];
    const float* w3  = (const float*)d_in[11];
    const float* b3  = (const float*)d_in[12];
    const float* g3  = (const float*)d_in[13];
    const float* be3 = (const float*)d_in[14];
    const float* wf  = (const float*)d_in[15];
    const float* bf  = (const float*)d_in[16];
    const float* gf  = (const float*)d_in[17];
    const float* bef = (const float*)d_in[18];
    float* out = (float*)d_out;

    k_init<<<1, 1>>>();
    k_conv1<<<(N1 + 255)/256, 256>>>(gather, w1);
    k_fin1<<<1, 1>>>(g1, be1);
    k_conv2<<<(N2 + 255)/256, 256>>>(w2, b2);
    k_fin2<<<1, 1>>>(g2, be2);
    k_conv3<<<(N3 + 255)/256, 256>>>(w3, b3);
    k_fin3<<<1, 1>>>(g3, be3);
    k_rowval<<<(MM*C3H + 255)/256, 256>>>();
    k_vint<<<(MM*HHH + 255)/256, 256>>>(cv, VMM);
    k_genr<<<(MM*RHH + 255)/256, 256>>>();
    k_statsF<<<BSZ*(RHH/TROWS), 256>>>(wf, bf);
    k_finF<<<1, 1>>>(gf, bef);
    k_outF<<<BSZ*(RHH/TROWS), 256>>>(wf, bf, out);
}

// round 6
// speedup vs baseline: 3.0994x; 1.1281x over previous
#include <cuda_runtime.h>
#include <math.h>

#define BSZ  8
#define KPS  8
#define NPK  16
#define TT   3072
#define WGW  64
#define HHH  256
#define WCC  256
#define RHH  1024
#define RWW  512
#define MM   64          // BSZ*KPS

#define C1H 1024
#define C1W 31
#define C2H 341
#define C2W 15
#define C3H 113
#define C3W 7

#define N1  (MM*C1H*C1W)     // 2031616
#define N2  (MM*C2H*C2W)     // 327360 per channel
#define N3  (MM*C3H*C3W)     // 50624
#define NF  (BSZ*RHH*RWW)    // 4194304

#define TROWS 16             // output rows per tile in the final stage

// conv2 tiling
#define R2   22              // output rows per strip
#define NS2  16              // strips per image (16*22=352 >= 341)
#define TR2  (3*R2 + 4)      // 70 input rows per tile

// ---------------- scratch (device globals; no allocation) ----------------
__device__ unsigned int g_maxbits;
__device__ double g_s1, g_q1;
__device__ double g_s2[2], g_q2[2];
__device__ double g_s3, g_q3;
__device__ double g_sf, g_qf;

__device__ float g_conv1[N1];        // RAW conv1 (no norm, no BN)
__device__ float g_conv2[2*N2];      // RAW conv2
__device__ float g_conv3[N3];        // RAW conv3
__device__ float g_genr[MM*RHH];
__device__ int   g_vint[MM*HHH];
__device__ float g_yraw[NF];         // raw conv_f output (pre-BN)

// ---------------- helpers ----------------
__device__ __forceinline__ float lrelu(float x){ return x >= 0.f ? x : 0.1f*x; }

__device__ __forceinline__ float warpSumF(float v){
#pragma unroll
    for (int o = 16; o > 0; o >>= 1) v += __shfl_down_sync(0xffffffffu, v, o);
    return v;
}
__device__ __forceinline__ float warpMaxF(float v){
#pragma unroll
    for (int o = 16; o > 0; o >>= 1) v = fmaxf(v, __shfl_down_sync(0xffffffffu, v, o));
    return v;
}

__device__ __forceinline__ void blockRedAdd2(float a, float b, double* da, double* db){
    a = warpSumF(a); b = warpSumF(b);
    __shared__ double sa[8], sb[8];
    int lane = threadIdx.x & 31, w = threadIdx.x >> 5;
    if (lane == 0){ sa[w] = (double)a; sb[w] = (double)b; }
    __syncthreads();
    if (w == 0){
        double x = (lane < 8) ? sa[lane] : 0.0;
        double y = (lane < 8) ? sb[lane] : 0.0;
#pragma unroll
        for (int o = 4; o > 0; o >>= 1){
            x += __shfl_down_sync(0xffffffffu, x, o);
            y += __shfl_down_sync(0xffffffffu, y, o);
        }
        if (lane == 0){ atomicAdd(da, x); atomicAdd(db, y); }
    }
    __syncthreads();
}

// ---------------- kernels ----------------
__global__ void k_init(){
    g_maxbits = 0u;
    g_s1 = 0; g_q1 = 0;
    g_s2[0] = 0; g_s2[1] = 0; g_q2[0] = 0; g_q2[1] = 0;
    g_s3 = 0; g_q3 = 0;
    g_sf = 0; g_qf = 0;
}

// conv1 RAW (no 1/max, no bias — both absorbed into BN1 affine) + maxabs + stats
__global__ void __launch_bounds__(256) k_conv1(const float* __restrict__ g,
                                               const float* __restrict__ w1){
    int idx = blockIdx.x*blockDim.x + threadIdx.x;
    float s = 0.f, q = 0.f, mx = 0.f;
    if (idx < N1){
        int j = idx % C1W; int t = idx / C1W; int i = t % C1H; int m = t / C1H;
        const float* base = g + (size_t)m*(TT*WGW) + (3*i)*WGW + 2*j;
        float w[9];
#pragma unroll
        for (int p = 0; p < 9; p++) w[p] = __ldg(&w1[p]);
        float acc = 0.f;
#pragma unroll
        for (int p = 0; p < 3; p++){
            const float* r = base + p*WGW;
            float a = r[0], bb = r[1], c = r[2];
            acc += w[p*3+0]*a + w[p*3+1]*bb + w[p*3+2]*c;
            mx = fmaxf(mx, fmaxf(fmaxf(fabsf(a), fabsf(bb)), fabsf(c)));
            if (j == C1W-1) mx = fmaxf(mx, fabsf(r[3]));   // col 63 coverage
        }
        g_conv1[idx] = acc;
        s = acc; q = acc*acc;
    }
    {
        float m = warpMaxF(mx);
        __shared__ float sm[8];
        int lane = threadIdx.x & 31, w = threadIdx.x >> 5;
        if (lane == 0) sm[w] = m;
        __syncthreads();
        if (w == 0){
            m = (lane < 8) ? sm[lane] : 0.f;
            m = warpMaxF(m);
            if (lane == 0) atomicMax(&g_maxbits, __float_as_uint(m));
        }
        __syncthreads();
    }
    blockRedAdd2(s, q, &g_s1, &g_q1);
}

// smem-tiled conv2: per block = one image m x 22-output-row strip.
// act tile -> rowmax3/rowmax5 line buffers -> conv with on-the-fly column max.
__global__ void __launch_bounds__(256) k_conv2(const float* __restrict__ w2,
                                               const float* __restrict__ b2,
                                               const float* __restrict__ g1,
                                               const float* __restrict__ be1){
    __shared__ float s_act[TR2][36];   // cols -2..32 at offsets 0..34
    __shared__ float s_rm3[TR2][32];   // rowmax3 at cols 0..30
    __shared__ float s_rm5[TR2][32];   // rowmax5 at cols 0..30
    __shared__ float s_ab[2];          // A1, B1

    int m     = blockIdx.x >> 4;
    int strip = blockIdx.x & 15;
    int i0    = strip * R2;
    int nout  = min(R2, C2H - i0);
    int tid   = threadIdx.x;

    if (tid == 0){
        double inv  = 1.0 / (double)__uint_as_float(g_maxbits);
        double mc   = g_s1 / (double)N1;
        double varc = g_q1 / (double)N1 - mc*mc;
        double istd = 1.0 / sqrt(inv*inv*varc + 1e-5);
        double A = inv*istd*(double)g1[0];
        s_ab[0] = (float)A;
        s_ab[1] = (float)((double)be1[0] - A*mc);
    }
    // pad columns
    for (int lr = tid; lr < TR2; lr += 256){
        s_act[lr][0] = -1e30f; s_act[lr][1] = -1e30f;
        s_act[lr][33] = -1e30f; s_act[lr][34] = -1e30f;
    }
    __syncthreads();
    float A1 = s_ab[0], B1 = s_ab[1];

    // load + activate tile
    int gr0 = 3*i0 - 2;
    const float* src = g_conv1 + m*(C1H*C1W);
    for (int idx = tid; idx < TR2*C1W; idx += 256){
        int lr = idx / C1W, c = idx % C1W;
        int gr = gr0 + lr;
        float v = -1e30f;
        if (gr >= 0 && gr < C1H)
            v = lrelu(src[gr*C1W + c]*A1 + B1);
        s_act[lr][c+2] = v;
    }
    __syncthreads();

    // row maxes
    for (int idx = tid; idx < TR2*C1W; idx += 256){
        int lr = idx / C1W, c = idx % C1W;
        float a0 = s_act[lr][c],   a1 = s_act[lr][c+1], a2 = s_act[lr][c+2];
        float a3 = s_act[lr][c+3], a4 = s_act[lr][c+4];
        s_rm3[lr][c] = fmaxf(a1, fmaxf(a2, a3));
        s_rm5[lr][c] = fmaxf(fmaxf(a0, a1), fmaxf(a2, fmaxf(a3, a4)));
    }
    __syncthreads();

    float w[54];
#pragma unroll
    for (int p = 0; p < 54; p++) w[p] = __ldg(&w2[p]);
    float bb0 = __ldg(&b2[0]), bb1 = __ldg(&b2[1]);

    float s0 = 0.f, q0 = 0.f, s1 = 0.f, q1 = 0.f;
    for (int o = tid; o < nout*C2W; o += 256){
        int oi = o / C2W, j = o % C2W;
        float acc0 = bb0, acc1 = bb1;
#pragma unroll
        for (int p = 0; p < 3; p++){
            int lr = 3*oi + p + 2;     // act row (smem-local)
#pragma unroll
            for (int qq = 0; qq < 3; qq++){
                int c = 2*j + qq;      // pool col index
                float v0 = s_act[lr][c+2];
                float p3 = fmaxf(s_rm3[lr-1][c], fmaxf(s_rm3[lr][c], s_rm3[lr+1][c]));
                float p5 = fmaxf(fmaxf(s_rm5[lr-2][c], s_rm5[lr-1][c]),
                                 fmaxf(s_rm5[lr][c], fmaxf(s_rm5[lr+1][c], s_rm5[lr+2][c])));
                int off = p*3 + qq;
                acc0 += w[off]*v0    + w[9+off]*p3  + w[18+off]*p5;
                acc1 += w[27+off]*v0 + w[36+off]*p3 + w[45+off]*p5;
            }
        }
        int i = i0 + oi;
        g_conv2[((m*2+0)*C2H + i)*C2W + j] = acc0;
        g_conv2[((m*2+1)*C2H + i)*C2W + j] = acc1;
        s0 += acc0; q0 += acc0*acc0;
        s1 += acc1; q1 += acc1*acc1;
    }
    blockRedAdd2(s0, q0, &g_s2[0], &g_q2[0]);
    blockRedAdd2(s1, q1, &g_s2[1], &g_q2[1]);
}

__global__ void __launch_bounds__(256) k_conv3(const float* __restrict__ w3,
                                               const float* __restrict__ b3,
                                               const float* __restrict__ g2,
                                               const float* __restrict__ be2){
    __shared__ float s_ab[4];
    if (threadIdx.x < 2){
        int c = threadIdx.x;
        double mn = g_s2[c] / (double)N2;
        double vr = g_q2[c] / (double)N2 - mn*mn;
        double sc = (double)g2[c] / sqrt(vr + 1e-5);
        s_ab[c]   = (float)sc;
        s_ab[2+c] = (float)((double)be2[c] - mn*sc);
    }
    __syncthreads();

    int idx = blockIdx.x*blockDim.x + threadIdx.x;
    float s = 0, q = 0;
    if (idx < N3){
        int j = idx % C3W; int t = idx / C3W; int i = t % C3H; int m = t / C3H;
        float acc = b3[0];
#pragma unroll
        for (int c = 0; c < 2; c++){
            float A2 = s_ab[c], B2 = s_ab[2+c];
            const float* B = g_conv2 + ((m*2+c)*C2H)*C2W;
#pragma unroll
            for (int p = 0; p < 3; p++){
#pragma unroll
                for (int qq = 0; qq < 2; qq++){
                    float raw = B[(3*i+p)*C2W + 2*j+qq];
                    acc += w3[c*6 + p*2 + qq]*lrelu(raw*A2 + B2);
                }
            }
        }
        g_conv3[idx] = acc;
        s = acc; q = acc*acc;
    }
    blockRedAdd2(s, q, &g_s3, &g_q3);
}

// fused rowval + genr + vint: one block per image m
__global__ void __launch_bounds__(256) k_mid(const float* __restrict__ cv,
                                             const float* __restrict__ VMM,
                                             const float* __restrict__ g3,
                                             const float* __restrict__ be3){
    __shared__ float s_rv[C3H];
    __shared__ float s_ab[2];
    int m = blockIdx.x;
    int tid = threadIdx.x;

    if (tid == 0){
        double mn = g_s3 / (double)N3;
        double vr = g_q3 / (double)N3 - mn*mn;
        double sc = (double)g3[0] / sqrt(vr + 1e-5);
        s_ab[0] = (float)sc;
        s_ab[1] = (float)((double)be3[0] - mn*sc);
    }
    __syncthreads();
    float A3 = s_ab[0], B3 = s_ab[1];

    if (tid < C3H){
        const float wcol[7] = {4.f/37.f, 5.f/37.f, 6.f/37.f, 7.f/37.f, 6.f/37.f, 5.f/37.f, 4.f/37.f};
        const float* B = g_conv3 + (m*C3H + tid)*C3W;
        float rv = 0.f;
#pragma unroll
        for (int j = 0; j < 7; j++)
            rv += wcol[j] * lrelu(B[j]*A3 + B3);
        s_rv[tid] = rv;
    }

    // vint (independent of rowval)
    if (tid < HHH){
        int b = m / KPS;
        const float* C = cv + m*NPK*2;
        const float dt = 7000.0f/255.0f;
        float vm0 = VMM[b*2];
        float dv = (VMM[b*2+1] - vm0)/255.0f;
        float tq = (float)tid;
        float tp = C[0]/dt, vp = (C[1] - vm0)/dv;
        float val;
        if (tq <= tp){
            val = vp;
        } else {
            val = (C[2*(NPK-1)+1] - vm0)/dv;
            for (int n = 1; n < NPK; n++){
                float tn = C[2*n]/dt, vn = (C[2*n+1] - vm0)/dv;
                if (tq <= tn){ val = vp + (vn - vp)*(tq - tp)/(tn - tp); break; }
                tp = tn; vp = vn;
            }
        }
        int vi = (int)val;
        g_vint[m*HHH + tid] = min(WCC-1, max(0, vi));
    }
    __syncthreads();

    // genr
    for (int rh = tid; rh < RHH; rh += 256){
        float ih = (rh + 0.5f)*(113.0f/1024.0f) - 0.5f;
        ih = fminf(fmaxf(ih, 0.f), 112.f);
        int h0 = (int)ih; float f = ih - (float)h0;
        int h1 = min(h0 + 1, 112);
        g_genr[m*RHH + rh] = (1.f - f)*s_rv[h0] + f*s_rv[h1];
    }
}

// fused mix + conv_f: compute raw y, store it, accumulate stats
__global__ void __launch_bounds__(256) k_statsF(const float* __restrict__ wf,
                                                const float* __restrict__ bf){
    __shared__ float s_mix[TROWS+2][RWW];
    __shared__ float s_g[TROWS+2][8];
    __shared__ int   s_v0[TROWS+2][8];
    __shared__ int   s_v1[TROWS+2][8];
    __shared__ float s_fh[TROWS+2];

    int b   = blockIdx.x / (RHH/TROWS);
    int rh0 = (blockIdx.x % (RHH/TROWS)) * TROWS;
    int tid = threadIdx.x;

    if (tid < (TROWS+2)*8){
        int r = tid >> 3, k = tid & 7;
        int gr = rh0 - 1 + r;
        float g = 0.f, fh = 0.f; int v0 = 0, v1 = 0;
        if (gr >= 0 && gr < RHH){
            float ih = (gr + 0.5f)*0.25f - 0.5f;
            ih = fminf(fmaxf(ih, 0.f), 255.f);
            int h0 = (int)ih; fh = ih - (float)h0; int h1 = min(h0 + 1, 255);
            int m = b*KPS + k;
            g  = g_genr[m*RHH + gr];
            v0 = g_vint[m*HHH + h0];
            v1 = g_vint[m*HHH + h1];
        }
        s_g[r][k] = g; s_v0[r][k] = v0; s_v1[r][k] = v1;
        if (k == 0) s_fh[r] = fh;
    }
    __syncthreads();

#pragma unroll
    for (int half = 0; half < 2; half++){
        int c = tid + half*256;
        float iw = (c + 0.5f)*0.5f - 0.5f;
        iw = fminf(fmaxf(iw, 0.f), 255.f);
        int c0 = (int)iw; float fw = iw - (float)c0; int c1 = min(c0 + 1, 255);
        for (int r = 0; r < TROWS+2; r++){
            float fh = s_fh[r];
            float acc = 0.f;
#pragma unroll
            for (int k = 0; k < 8; k++){
                float g = s_g[r][k];
                int v0 = s_v0[r][k], v1 = s_v1[r][k];
                float s0 = (c0 == v0 ? 1.f - fw : 0.f) + (c1 == v0 ? fw : 0.f);
                float s1 = (c0 == v1 ? 1.f - fw : 0.f) + (c1 == v1 ? fw : 0.f);
                acc += g*(0.01f + 0.9f*((1.f - fh)*s0 + fh*s1));
            }
            s_mix[r][c] = acc;
        }
    }
    __syncthreads();

    float W[9];
#pragma unroll
    for (int i = 0; i < 9; i++) W[i] = __ldg(&wf[i]);
    float bb = __ldg(&bf[0]);

    float s = 0.f, q = 0.f;
    for (int orow = 0; orow < TROWS; orow++){
#pragma unroll
        for (int half = 0; half < 2; half++){
            int c = tid + half*256;
            float acc = bb;
#pragma unroll
            for (int p = 0; p < 3; p++){
#pragma unroll
                for (int qq = 0; qq < 3; qq++){
                    int cc = c - 1 + qq;
                    if (cc >= 0 && cc < RWW)
                        acc += W[p*3+qq]*s_mix[orow+p][cc];
                }
            }
            g_yraw[((size_t)b*RHH + rh0 + orow)*RWW + c] = acc;
            s += acc; q += acc*acc;
        }
    }
    blockRedAdd2(s, q, &g_sf, &g_qf);
}

// elementwise: out = lrelu(yraw*sc + sh), float4
__global__ void __launch_bounds__(256) k_final(const float* __restrict__ gf,
                                               const float* __restrict__ bef,
                                               float* __restrict__ out){
    __shared__ float s_ab[2];
    if (threadIdx.x == 0){
        double mn = g_sf / (double)NF;
        double vr = g_qf / (double)NF - mn*mn;
        double sc = (double)gf[0] / sqrt(vr + 1e-5);
        s_ab[0] = (float)sc;
        s_ab[1] = (float)((double)bef[0] - mn*sc);
    }
    __syncthreads();
    float sc = s_ab[0], sh = s_ab[1];

    int i = blockIdx.x*blockDim.x + threadIdx.x;
    if (i < NF/4){
        float4 y = ((const float4*)g_yraw)[i];
        float4 o;
        o.x = lrelu(y.x*sc + sh);
        o.y = lrelu(y.y*sc + sh);
        o.z = lrelu(y.z*sc + sh);
        o.w = lrelu(y.w*sc + sh);
        ((float4*)out)[i] = o;
    }
}

// ---------------- launch ----------------
extern "C" void kernel_launch(void* const* d_in, const int* in_sizes, int n_in,
                              void* d_out, int out_size){
    const float* gather = (const float*)d_in[0];
    const float* cv     = (const float*)d_in[1];
    const float* VMM    = (const float*)d_in[2];
    const float* w1  = (const float*)d_in[3];
    const float* g1  = (const float*)d_in[5];
    const float* be1 = (const float*)d_in[6];
    const float* w2  = (const float*)d_in[7];
    const float* b2  = (const float*)d_in[8];
    const float* g2  = (const float*)d_in[9];
    const float* be2 = (const float*)d_in[10];
    const float* w3  = (const float*)d_in[11];
    const float* b3  = (const float*)d_in[12];
    const float* g3  = (const float*)d_in[13];
    const float* be3 = (const float*)d_in[14];
    const float* wf  = (const float*)d_in[15];
    const float* bf  = (const float*)d_in[16];
    const float* gf  = (const float*)d_in[17];
    const float* bef = (const float*)d_in[18];
    float* out = (float*)d_out;

    k_init<<<1, 1>>>();
    k_conv1<<<(N1 + 255)/256, 256>>>(gather, w1);
    k_conv2<<<MM*NS2, 256>>>(w2, b2, g1, be1);
    k_conv3<<<(N3 + 255)/256, 256>>>(w3, b3, g2, be2);
    k_mid<<<MM, 256>>>(cv, VMM, g3, be3);
    k_statsF<<<BSZ*(RHH/TROWS), 256>>>(wf, bf);
    k_final<<<NF/4/256, 256>>>(gf, bef, out);
}

// round 8
// speedup vs baseline: 5.0970x; 1.6445x over previous
#include <cuda_runtime.h>
#include <math.h>

#define BSZ  8
#define KPS  8
#define NPK  16
#define TT   3072
#define WGW  64
#define HHH  256
#define WCC  256
#define RHH  1024
#define RWW  512
#define MM   64          // BSZ*KPS

#define C1H 1024
#define C1W 31
#define C2H 341
#define C2W 15
#define C3H 113
#define C3W 7

#define N1  (MM*C1H*C1W)     // 2031616
#define N2  (MM*C2H*C2W)     // 327360 per channel
#define N3  (MM*C3H*C3W)     // 50624
#define NF  (BSZ*RHH*RWW)    // 4194304

#define TROWS 16             // output rows per tile in the final stage

// conv1 tiling
#define S1ROWS 32            // output rows per strip
#define S1IN   (3*S1ROWS)    // 96 input rows
#define NS1    (C1H/S1ROWS)  // 32 strips per image

// conv2 tiling
#define R2   22              // output rows per strip
#define NS2  16              // strips per image (16*22=352 >= 341)
#define TR2  (3*R2 + 4)      // 70 input rows per tile

// ---------------- scratch (device globals; no allocation) ----------------
__device__ unsigned int g_maxbits;
__device__ double g_s1, g_q1;
__device__ double g_s2[2], g_q2[2];
__device__ double g_s3, g_q3;
__device__ double g_sf, g_qf;

__device__ float g_conv1[N1];        // RAW conv1 (no norm, no BN)
__device__ float g_conv2[2*N2];      // RAW conv2
__device__ float g_conv3[N3];        // RAW conv3
__device__ float g_genr[MM*RHH];
__device__ int   g_vint[MM*HHH];
__device__ float g_yraw[NF];         // raw conv_f output (pre-BN)

// ---------------- helpers ----------------
__device__ __forceinline__ float lrelu(float x){ return x >= 0.f ? x : 0.1f*x; }

__device__ __forceinline__ float warpSumF(float v){
#pragma unroll
    for (int o = 16; o > 0; o >>= 1) v += __shfl_down_sync(0xffffffffu, v, o);
    return v;
}
__device__ __forceinline__ float warpMaxF(float v){
#pragma unroll
    for (int o = 16; o > 0; o >>= 1) v = fmaxf(v, __shfl_down_sync(0xffffffffu, v, o));
    return v;
}

// 256-thread block reduction of (a,b) -> double atomics
__device__ __forceinline__ void blockRedAdd2(float a, float b, double* da, double* db){
    a = warpSumF(a); b = warpSumF(b);
    __shared__ double sa[8], sb[8];
    int lane = threadIdx.x & 31, w = threadIdx.x >> 5;
    if (lane == 0){ sa[w] = (double)a; sb[w] = (double)b; }
    __syncthreads();
    if (w == 0){
        double x = (lane < 8) ? sa[lane] : 0.0;
        double y = (lane < 8) ? sb[lane] : 0.0;
#pragma unroll
        for (int o = 4; o > 0; o >>= 1){
            x += __shfl_down_sync(0xffffffffu, x, o);
            y += __shfl_down_sync(0xffffffffu, y, o);
        }
        if (lane == 0){ atomicAdd(da, x); atomicAdd(db, y); }
    }
    __syncthreads();
}

// 128-thread variant
__device__ __forceinline__ void blockRedAdd2_128(float a, float b, double* da, double* db){
    a = warpSumF(a); b = warpSumF(b);
    __shared__ double sa[4], sb[4];
    int lane = threadIdx.x & 31, w = threadIdx.x >> 5;
    if (lane == 0){ sa[w] = (double)a; sb[w] = (double)b; }
    __syncthreads();
    if (w == 0){
        double x = (lane < 4) ? sa[lane] : 0.0;
        double y = (lane < 4) ? sb[lane] : 0.0;
#pragma unroll
        for (int o = 2; o > 0; o >>= 1){
            x += __shfl_down_sync(0xffffffffu, x, o);
            y += __shfl_down_sync(0xffffffffu, y, o);
        }
        if (lane == 0){ atomicAdd(da, x); atomicAdd(db, y); }
    }
    __syncthreads();
}

// ---------------- kernels ----------------
__global__ void k_init(){
    g_maxbits = 0u;
    g_s1 = 0; g_q1 = 0;
    g_s2[0] = 0; g_s2[1] = 0; g_q2[0] = 0; g_q2[1] = 0;
    g_s3 = 0; g_q3 = 0;
    g_sf = 0; g_qf = 0;
}

// smem-tiled conv1 RAW + maxabs + stats. Block = image m x 32-output-row strip.
__global__ void __launch_bounds__(256) k_conv1(const float* __restrict__ g,
                                               const float* __restrict__ w1){
    __shared__ float s_in[S1IN][WGW];   // 96*64*4 = 24 KB

    int m     = blockIdx.x >> 5;
    int strip = blockIdx.x & 31;
    int i0    = strip * S1ROWS;
    int tid   = threadIdx.x;

    const float4* src = (const float4*)(g + (size_t)m*(TT*WGW) + (size_t)(3*i0)*WGW);

    float mx = 0.f;
#pragma unroll
    for (int k = 0; k < (S1IN*16)/256; k++){       // 6 iterations
        int idx = tid + k*256;
        float4 v = src[idx];
        int row = idx >> 4, c4 = idx & 15;
        s_in[row][c4*4+0] = v.x;
        s_in[row][c4*4+1] = v.y;
        s_in[row][c4*4+2] = v.z;
        s_in[row][c4*4+3] = v.w;
        mx = fmaxf(mx, fmaxf(fmaxf(fabsf(v.x), fabsf(v.y)), fmaxf(fabsf(v.z), fabsf(v.w))));
    }
    __syncthreads();

    float w[9];
#pragma unroll
    for (int p = 0; p < 9; p++) w[p] = __ldg(&w1[p]);

    float s = 0.f, q = 0.f;
    for (int o = tid; o < S1ROWS*C1W; o += 256){
        int oi = o / C1W, j = o % C1W;
        int r0 = 3*oi, c0 = 2*j;
        float acc = 0.f;
#pragma unroll
        for (int p = 0; p < 3; p++){
            acc += w[p*3+0]*s_in[r0+p][c0]
                 + w[p*3+1]*s_in[r0+p][c0+1]
                 + w[p*3+2]*s_in[r0+p][c0+2];
        }
        g_conv1[((size_t)m*C1H + i0 + oi)*C1W + j] = acc;
        s += acc; q += acc*acc;
    }

    // block max -> atomicMax
    {
        float mm = warpMaxF(mx);
        __shared__ float sm[8];
        int lane = threadIdx.x & 31, wp = threadIdx.x >> 5;
        if (lane == 0) sm[wp] = mm;
        __syncthreads();
        if (wp == 0){
            mm = (lane < 8) ? sm[lane] : 0.f;
            mm = warpMaxF(mm);
            if (lane == 0) atomicMax(&g_maxbits, __float_as_uint(mm));
        }
        __syncthreads();
    }
    blockRedAdd2(s, q, &g_s1, &g_q1);
}

// smem-tiled conv2 (separable pooling)
__global__ void __launch_bounds__(256) k_conv2(const float* __restrict__ w2,
                                               const float* __restrict__ b2,
                                               const float* __restrict__ g1,
                                               const float* __restrict__ be1){
    __shared__ float s_act[TR2][36];   // cols -2..32 at offsets 0..34
    __shared__ float s_rm3[TR2][32];
    __shared__ float s_rm5[TR2][32];
    __shared__ float s_ab[2];

    int m     = blockIdx.x >> 4;
    int strip = blockIdx.x & 15;
    int i0    = strip * R2;
    int nout  = min(R2, C2H - i0);
    int tid   = threadIdx.x;

    if (tid == 0){
        double inv  = 1.0 / (double)__uint_as_float(g_maxbits);
        double mc   = g_s1 / (double)N1;
        double varc = g_q1 / (double)N1 - mc*mc;
        double istd = 1.0 / sqrt(inv*inv*varc + 1e-5);
        double A = inv*istd*(double)g1[0];
        s_ab[0] = (float)A;
        s_ab[1] = (float)((double)be1[0] - A*mc);
    }
    for (int lr = tid; lr < TR2; lr += 256){
        s_act[lr][0] = -1e30f; s_act[lr][1] = -1e30f;
        s_act[lr][33] = -1e30f; s_act[lr][34] = -1e30f;
    }
    __syncthreads();
    float A1 = s_ab[0], B1 = s_ab[1];

    int gr0 = 3*i0 - 2;
    const float* src = g_conv1 + (size_t)m*(C1H*C1W);
    for (int idx = tid; idx < TR2*C1W; idx += 256){
        int lr = idx / C1W, c = idx % C1W;
        int gr = gr0 + lr;
        float v = -1e30f;
        if (gr >= 0 && gr < C1H)
            v = lrelu(src[gr*C1W + c]*A1 + B1);
        s_act[lr][c+2] = v;
    }
    __syncthreads();

    for (int idx = tid; idx < TR2*C1W; idx += 256){
        int lr = idx / C1W, c = idx % C1W;
        float a0 = s_act[lr][c],   a1 = s_act[lr][c+1], a2 = s_act[lr][c+2];
        float a3 = s_act[lr][c+3], a4 = s_act[lr][c+4];
        s_rm3[lr][c] = fmaxf(a1, fmaxf(a2, a3));
        s_rm5[lr][c] = fmaxf(fmaxf(a0, a1), fmaxf(a2, fmaxf(a3, a4)));
    }
    __syncthreads();

    float w[54];
#pragma unroll
    for (int p = 0; p < 54; p++) w[p] = __ldg(&w2[p]);
    float bb0 = __ldg(&b2[0]), bb1 = __ldg(&b2[1]);

    float s0 = 0.f, q0 = 0.f, s1 = 0.f, q1 = 0.f;
    for (int o = tid; o < nout*C2W; o += 256){
        int oi = o / C2W, j = o % C2W;
        float acc0 = bb0, acc1 = bb1;
#pragma unroll
        for (int p = 0; p < 3; p++){
            int lr = 3*oi + p + 2;
#pragma unroll
            for (int qq = 0; qq < 3; qq++){
                int c = 2*j + qq;
                float v0 = s_act[lr][c+2];
                float p3 = fmaxf(s_rm3[lr-1][c], fmaxf(s_rm3[lr][c], s_rm3[lr+1][c]));
                float p5 = fmaxf(fmaxf(s_rm5[lr-2][c], s_rm5[lr-1][c]),
                                 fmaxf(s_rm5[lr][c], fmaxf(s_rm5[lr+1][c], s_rm5[lr+2][c])));
                int off = p*3 + qq;
                acc0 += w[off]*v0    + w[9+off]*p3  + w[18+off]*p5;
                acc1 += w[27+off]*v0 + w[36+off]*p3 + w[45+off]*p5;
            }
        }
        int i = i0 + oi;
        g_conv2[((m*2+0)*C2H + i)*C2W + j] = acc0;
        g_conv2[((m*2+1)*C2H + i)*C2W + j] = acc1;
        s0 += acc0; q0 += acc0*acc0;
        s1 += acc1; q1 += acc1*acc1;
    }
    blockRedAdd2(s0, q0, &g_s2[0], &g_q2[0]);
    blockRedAdd2(s1, q1, &g_s2[1], &g_q2[1]);
}

// conv3: 128-thread blocks for wider spread
__global__ void __launch_bounds__(128) k_conv3(const float* __restrict__ w3,
                                               const float* __restrict__ b3,
                                               const float* __restrict__ g2,
                                               const float* __restrict__ be2){
    __shared__ float s_ab[4];
    if (threadIdx.x < 2){
        int c = threadIdx.x;
        double mn = g_s2[c] / (double)N2;
        double vr = g_q2[c] / (double)N2 - mn*mn;
        double sc = (double)g2[c] / sqrt(vr + 1e-5);
        s_ab[c]   = (float)sc;
        s_ab[2+c] = (float)((double)be2[c] - mn*sc);
    }
    __syncthreads();

    int idx = blockIdx.x*blockDim.x + threadIdx.x;
    float s = 0, q = 0;
    if (idx < N3){
        int j = idx % C3W; int t = idx / C3W; int i = t % C3H; int m = t / C3H;
        float acc = b3[0];
#pragma unroll
        for (int c = 0; c < 2; c++){
            float A2 = s_ab[c], B2 = s_ab[2+c];
            const float* B = g_conv2 + ((m*2+c)*C2H)*C2W;
#pragma unroll
            for (int p = 0; p < 3; p++){
#pragma unroll
                for (int qq = 0; qq < 2; qq++){
                    float raw = B[(3*i+p)*C2W + 2*j+qq];
                    acc += w3[c*6 + p*2 + qq]*lrelu(raw*A2 + B2);
                }
            }
        }
        g_conv3[idx] = acc;
        s = acc; q = acc*acc;
    }
    blockRedAdd2_128(s, q, &g_s3, &g_q3);
}

// fused rowval + genr + vint: 4 blocks per image (quarter of genr rows each)
__global__ void __launch_bounds__(256) k_mid(const float* __restrict__ cv,
                                             const float* __restrict__ VMM,
                                             const float* __restrict__ g3,
                                             const float* __restrict__ be3){
    __shared__ float s_rv[C3H];
    __shared__ float s_ab[2];
    int m   = blockIdx.x >> 2;
    int qtr = blockIdx.x & 3;
    int tid = threadIdx.x;

    if (tid == 0){
        double mn = g_s3 / (double)N3;
        double vr = g_q3 / (double)N3 - mn*mn;
        double sc = (double)g3[0] / sqrt(vr + 1e-5);
        s_ab[0] = (float)sc;
        s_ab[1] = (float)((double)be3[0] - mn*sc);
    }
    __syncthreads();
    float A3 = s_ab[0], B3 = s_ab[1];

    if (tid < C3H){
        const float wcol[7] = {4.f/37.f, 5.f/37.f, 6.f/37.f, 7.f/37.f, 6.f/37.f, 5.f/37.f, 4.f/37.f};
        const float* B = g_conv3 + (m*C3H + tid)*C3W;
        float rv = 0.f;
#pragma unroll
        for (int j = 0; j < 7; j++)
            rv += wcol[j] * lrelu(B[j]*A3 + B3);
        s_rv[tid] = rv;
    }

    if (qtr == 0){
        int b = m / KPS;
        const float* C = cv + m*NPK*2;
        const float dt = 7000.0f/255.0f;
        float vm0 = VMM[b*2];
        float dv = (VMM[b*2+1] - vm0)/255.0f;
        float tq = (float)tid;
        float tp = C[0]/dt, vp = (C[1] - vm0)/dv;
        float val;
        if (tq <= tp){
            val = vp;
        } else {
            val = (C[2*(NPK-1)+1] - vm0)/dv;
            for (int n = 1; n < NPK; n++){
                float tn = C[2*n]/dt, vn = (C[2*n+1] - vm0)/dv;
                if (tq <= tn){ val = vp + (vn - vp)*(tq - tp)/(tn - tp); break; }
                tp = tn; vp = vn;
            }
        }
        int vi = (int)val;
        g_vint[m*HHH + tid] = min(WCC-1, max(0, vi));
    }
    __syncthreads();

    int rh = qtr*256 + tid;
    float ih = (rh + 0.5f)*(113.0f/1024.0f) - 0.5f;
    ih = fminf(fmaxf(ih, 0.f), 112.f);
    int h0 = (int)ih; float f = ih - (float)h0;
    int h1 = min(h0 + 1, 112);
    g_genr[m*RHH + rh] = (1.f - f)*s_rv[h0] + f*s_rv[h1];
}

// fused mix + conv_f: compute raw y, store it, accumulate stats
__global__ void __launch_bounds__(256) k_statsF(const float* __restrict__ wf,
                                                const float* __restrict__ bf){
    __shared__ float s_mix[TROWS+2][RWW];
    __shared__ float s_g[TROWS+2][8];
    __shared__ int   s_v0[TROWS+2][8];
    __shared__ int   s_v1[TROWS+2][8];
    __shared__ float s_fh[TROWS+2];

    int b   = blockIdx.x / (RHH/TROWS);
    int rh0 = (blockIdx.x % (RHH/TROWS)) * TROWS;
    int tid = threadIdx.x;

    if (tid < (TROWS+2)*8){
        int r = tid >> 3, k = tid & 7;
        int gr = rh0 - 1 + r;
        float g = 0.f, fh = 0.f; int v0 = 0, v1 = 0;
        if (gr >= 0 && gr < RHH){
            float ih = (gr + 0.5f)*0.25f - 0.5f;
            ih = fminf(fmaxf(ih, 0.f), 255.f);
            int h0 = (int)ih; fh = ih - (float)h0; int h1 = min(h0 + 1, 255);
            int m = b*KPS + k;
            g  = g_genr[m*RHH + gr];
            v0 = g_vint[m*HHH + h0];
            v1 = g_vint[m*HHH + h1];
        }
        s_g[r][k] = g; s_v0[r][k] = v0; s_v1[r][k] = v1;
        if (k == 0) s_fh[r] = fh;
    }
    __syncthreads();

#pragma unroll
    for (int half = 0; half < 2; half++){
        int c = tid + half*256;
        float iw = (c + 0.5f)*0.5f - 0.5f;
        iw = fminf(fmaxf(iw, 0.f), 255.f);
        int c0 = (int)iw; float fw = iw - (float)c0; int c1 = min(c0 + 1, 255);
        for (int r = 0; r < TROWS+2; r++){
            float fh = s_fh[r];
            float acc = 0.f;
#pragma unroll
            for (int k = 0; k < 8; k++){
                float g = s_g[r][k];
                int v0 = s_v0[r][k], v1 = s_v1[r][k];
                float s0 = (c0 == v0 ? 1.f - fw : 0.f) + (c1 == v0 ? fw : 0.f);
                float s1 = (c0 == v1 ? 1.f - fw : 0.f) + (c1 == v1 ? fw : 0.f);
                acc += g*(0.01f + 0.9f*((1.f - fh)*s0 + fh*s1));
            }
            s_mix[r][c] = acc;
        }
    }
    __syncthreads();

    float W[9];
#pragma unroll
    for (int i = 0; i < 9; i++) W[i] = __ldg(&wf[i]);
    float bb = __ldg(&bf[0]);

    float s = 0.f, q = 0.f;
    for (int orow = 0; orow < TROWS; orow++){
#pragma unroll
        for (int half = 0; half < 2; half++){
            int c = tid + half*256;
            float acc = bb;
#pragma unroll
            for (int p = 0; p < 3; p++){
#pragma unroll
                for (int qq = 0; qq < 3; qq++){
                    int cc = c - 1 + qq;
                    if (cc >= 0 && cc < RWW)
                        acc += W[p*3+qq]*s_mix[orow+p][cc];
                }
            }
            g_yraw[((size_t)b*RHH + rh0 + orow)*RWW + c] = acc;
            s += acc; q += acc*acc;
        }
    }
    blockRedAdd2(s, q, &g_sf, &g_qf);
}

// elementwise: out = lrelu(yraw*sc + sh), float4
__global__ void __launch_bounds__(256) k_final(const float* __restrict__ gf,
                                               const float* __restrict__ bef,
                                               float* __restrict__ out){
    __shared__ float s_ab[2];
    if (threadIdx.x == 0){
        double mn = g_sf / (double)NF;
        double vr = g_qf / (double)NF - mn*mn;
        double sc = (double)gf[0] / sqrt(vr + 1e-5);
        s_ab[0] = (float)sc;
        s_ab[1] = (float)((double)bef[0] - mn*sc);
    }
    __syncthreads();
    float sc = s_ab[0], sh = s_ab[1];

    int i = blockIdx.x*blockDim.x + threadIdx.x;
    if (i < NF/4){
        float4 y = ((const float4*)g_yraw)[i];
        float4 o;
        o.x = lrelu(y.x*sc + sh);
        o.y = lrelu(y.y*sc + sh);
        o.z = lrelu(y.z*sc + sh);
        o.w = lrelu(y.w*sc + sh);
        ((float4*)out)[i] = o;
    }
}

// ---------------- launch ----------------
extern "C" void kernel_launch(void* const* d_in, const int* in_sizes, int n_in,
                              void* d_out, int out_size){
    const float* gather = (const float*)d_in[0];
    const float* cv     = (const float*)d_in[1];
    const float* VMM    = (const float*)d_in[2];
    const float* w1  = (const float*)d_in[3];
    const float* g1  = (const float*)d_in[5];
    const float* be1 = (const float*)d_in[6];
    const float* w2  = (const float*)d_in[7];
    const float* b2  = (const float*)d_in[8];
    const float* g2  = (const float*)d_in[9];
    const float* be2 = (const float*)d_in[10];
    const float* w3  = (const float*)d_in[11];
    const float* b3  = (const float*)d_in[12];
    const float* g3  = (const float*)d_in[13];
    const float* be3 = (const float*)d_in[14];
    const float* wf  = (const float*)d_in[15];
    const float* bf  = (const float*)d_in[16];
    const float* gf  = (const float*)d_in[17];
    const float* bef = (const float*)d_in[18];
    float* out = (float*)d_out;

    k_init<<<1, 1>>>();
    k_conv1<<<MM*NS1, 256>>>(gather, w1);
    k_conv2<<<MM*NS2, 256>>>(w2, b2, g1, be1);
    k_conv3<<<(N3 + 127)/128, 128>>>(w3, b3, g2, be2);
    k_mid<<<MM*4, 256>>>(cv, VMM, g3, be3);
    k_statsF<<<BSZ*(RHH/TROWS), 256>>>(wf, bf);
    k_final<<<NF/4/256, 256>>>(gf, bef, out);
}

// round 10
// speedup vs baseline: 5.7609x; 1.1303x over previous
#include <cuda_runtime.h>
#include <math.h>

#define BSZ  8
#define KPS  8
#define NPK  16
#define TT   3072
#define WGW  64
#define HHH  256
#define WCC  256
#define RHH  1024
#define RWW  512
#define MM   64          // BSZ*KPS

#define C1H 1024
#define C1W 31
#define C2H 341
#define C2W 15
#define C3H 113
#define C3W 7

#define N1  (MM*C1H*C1W)     // 2031616
#define N2  (MM*C2H*C2W)     // 327360 per channel
#define N3  (MM*C3H*C3W)     // 50624
#define NF  (BSZ*RHH*RWW)    // 4194304

#define TROWS 16             // output rows per tile in the final stage

// conv1 tiling
#define S1ROWS 32            // output rows per strip
#define S1IN   (3*S1ROWS)    // 96 input rows
#define NS1    (C1H/S1ROWS)  // 32 strips per image

// conv2 tiling
#define R2   22              // output rows per strip
#define NS2  16              // strips per image (16*22=352 >= 341)
#define TR2  (3*R2 + 4)      // 70 input rows per tile

// conv3 tiling: block = (image, half). half 0: rows [0,57), half 1: [57,113)
#define C3HALF 57
#define C3INMAX 171          // 3*57 input rows max

// ---------------- scratch (device globals; no allocation) ----------------
__device__ unsigned int g_maxbits;
__device__ double g_s1, g_q1;
__device__ double g_s2[2], g_q2[2];
__device__ double g_s3, g_q3;
__device__ double g_sf, g_qf;

__device__ float g_conv1[N1];        // RAW conv1 (no norm, no BN)
__device__ float g_conv2[2*N2];      // RAW conv2
__device__ float g_conv3[N3];        // RAW conv3
__device__ float g_genr[MM*RHH];
__device__ int   g_vint[MM*HHH];
__device__ float g_yraw[NF];         // raw conv_f output (pre-BN)

// ---------------- helpers ----------------
__device__ __forceinline__ float lrelu(float x){ return x >= 0.f ? x : 0.1f*x; }

__device__ __forceinline__ float warpSumF(float v){
#pragma unroll
    for (int o = 16; o > 0; o >>= 1) v += __shfl_down_sync(0xffffffffu, v, o);
    return v;
}
__device__ __forceinline__ float warpMaxF(float v){
#pragma unroll
    for (int o = 16; o > 0; o >>= 1) v = fmaxf(v, __shfl_down_sync(0xffffffffu, v, o));
    return v;
}

// 256-thread block reduction of (a,b) -> double atomics
__device__ __forceinline__ void blockRedAdd2(float a, float b, double* da, double* db){
    a = warpSumF(a); b = warpSumF(b);
    __shared__ double sa[8], sb[8];
    int lane = threadIdx.x & 31, w = threadIdx.x >> 5;
    if (lane == 0){ sa[w] = (double)a; sb[w] = (double)b; }
    __syncthreads();
    if (w == 0){
        double x = (lane < 8) ? sa[lane] : 0.0;
        double y = (lane < 8) ? sb[lane] : 0.0;
#pragma unroll
        for (int o = 4; o > 0; o >>= 1){
            x += __shfl_down_sync(0xffffffffu, x, o);
            y += __shfl_down_sync(0xffffffffu, y, o);
        }
        if (lane == 0){ atomicAdd(da, x); atomicAdd(db, y); }
    }
    __syncthreads();
}

// ---------------- kernels ----------------
__global__ void k_init(){
    g_maxbits = 0u;
    g_s1 = 0; g_q1 = 0;
    g_s2[0] = 0; g_s2[1] = 0; g_q2[0] = 0; g_q2[1] = 0;
    g_s3 = 0; g_q3 = 0;
    g_sf = 0; g_qf = 0;
}

// smem-tiled conv1 RAW + maxabs + stats. Block = image m x 32-output-row strip.
__global__ void __launch_bounds__(256) k_conv1(const float* __restrict__ g,
                                               const float* __restrict__ w1){
    __shared__ float s_in[S1IN][WGW];   // 24 KB

    int m     = blockIdx.x >> 5;
    int strip = blockIdx.x & 31;
    int i0    = strip * S1ROWS;
    int tid   = threadIdx.x;

    const float4* src = (const float4*)(g + (size_t)m*(TT*WGW) + (size_t)(3*i0)*WGW);

    float mx = 0.f;
#pragma unroll
    for (int k = 0; k < (S1IN*16)/256; k++){       // 6 iterations
        int idx = tid + k*256;
        float4 v = src[idx];
        int row = idx >> 4, c4 = idx & 15;
        s_in[row][c4*4+0] = v.x;
        s_in[row][c4*4+1] = v.y;
        s_in[row][c4*4+2] = v.z;
        s_in[row][c4*4+3] = v.w;
        mx = fmaxf(mx, fmaxf(fmaxf(fabsf(v.x), fabsf(v.y)), fmaxf(fabsf(v.z), fabsf(v.w))));
    }
    __syncthreads();

    float w[9];
#pragma unroll
    for (int p = 0; p < 9; p++) w[p] = __ldg(&w1[p]);

    float s = 0.f, q = 0.f;
    for (int o = tid; o < S1ROWS*C1W; o += 256){
        int oi = o / C1W, j = o % C1W;
        int r0 = 3*oi, c0 = 2*j;
        float acc = 0.f;
#pragma unroll
        for (int p = 0; p < 3; p++){
            acc += w[p*3+0]*s_in[r0+p][c0]
                 + w[p*3+1]*s_in[r0+p][c0+1]
                 + w[p*3+2]*s_in[r0+p][c0+2];
        }
        g_conv1[((size_t)m*C1H + i0 + oi)*C1W + j] = acc;
        s += acc; q += acc*acc;
    }

    {
        float mm = warpMaxF(mx);
        __shared__ float sm[8];
        int lane = threadIdx.x & 31, wp = threadIdx.x >> 5;
        if (lane == 0) sm[wp] = mm;
        __syncthreads();
        if (wp == 0){
            mm = (lane < 8) ? sm[lane] : 0.f;
            mm = warpMaxF(mm);
            if (lane == 0) atomicMax(&g_maxbits, __float_as_uint(mm));
        }
        __syncthreads();
    }
    blockRedAdd2(s, q, &g_s1, &g_q1);
}

// smem-tiled conv2 (separable pooling)
__global__ void __launch_bounds__(256) k_conv2(const float* __restrict__ w2,
                                               const float* __restrict__ b2,
                                               const float* __restrict__ g1,
                                               const float* __restrict__ be1){
    __shared__ float s_act[TR2][36];
    __shared__ float s_rm3[TR2][32];
    __shared__ float s_rm5[TR2][32];
    __shared__ float s_ab[2];

    int m     = blockIdx.x >> 4;
    int strip = blockIdx.x & 15;
    int i0    = strip * R2;
    int nout  = min(R2, C2H - i0);
    int tid   = threadIdx.x;

    if (tid == 0){
        double inv  = 1.0 / (double)__uint_as_float(g_maxbits);
        double mc   = g_s1 / (double)N1;
        double varc = g_q1 / (double)N1 - mc*mc;
        double istd = 1.0 / sqrt(inv*inv*varc + 1e-5);
        double A = inv*istd*(double)g1[0];
        s_ab[0] = (float)A;
        s_ab[1] = (float)((double)be1[0] - A*mc);
    }
    for (int lr = tid; lr < TR2; lr += 256){
        s_act[lr][0] = -1e30f; s_act[lr][1] = -1e30f;
        s_act[lr][33] = -1e30f; s_act[lr][34] = -1e30f;
    }
    __syncthreads();
    float A1 = s_ab[0], B1 = s_ab[1];

    int gr0 = 3*i0 - 2;
    const float* src = g_conv1 + (size_t)m*(C1H*C1W);
    for (int idx = tid; idx < TR2*C1W; idx += 256){
        int lr = idx / C1W, c = idx % C1W;
        int gr = gr0 + lr;
        float v = -1e30f;
        if (gr >= 0 && gr < C1H)
            v = lrelu(src[gr*C1W + c]*A1 + B1);
        s_act[lr][c+2] = v;
    }
    __syncthreads();

    for (int idx = tid; idx < TR2*C1W; idx += 256){
        int lr = idx / C1W, c = idx % C1W;
        float a0 = s_act[lr][c],   a1 = s_act[lr][c+1], a2 = s_act[lr][c+2];
        float a3 = s_act[lr][c+3], a4 = s_act[lr][c+4];
        s_rm3[lr][c] = fmaxf(a1, fmaxf(a2, a3));
        s_rm5[lr][c] = fmaxf(fmaxf(a0, a1), fmaxf(a2, fmaxf(a3, a4)));
    }
    __syncthreads();

    float w[54];
#pragma unroll
    for (int p = 0; p < 54; p++) w[p] = __ldg(&w2[p]);
    float bb0 = __ldg(&b2[0]), bb1 = __ldg(&b2[1]);

    float s0 = 0.f, q0 = 0.f, s1 = 0.f, q1 = 0.f;
    for (int o = tid; o < nout*C2W; o += 256){
        int oi = o / C2W, j = o % C2W;
        float acc0 = bb0, acc1 = bb1;
#pragma unroll
        for (int p = 0; p < 3; p++){
            int lr = 3*oi + p + 2;
#pragma unroll
            for (int qq = 0; qq < 3; qq++){
                int c = 2*j + qq;
                float v0 = s_act[lr][c+2];
                float p3 = fmaxf(s_rm3[lr-1][c], fmaxf(s_rm3[lr][c], s_rm3[lr+1][c]));
                float p5 = fmaxf(fmaxf(s_rm5[lr-2][c], s_rm5[lr-1][c]),
                                 fmaxf(s_rm5[lr][c], fmaxf(s_rm5[lr+1][c], s_rm5[lr+2][c])));
                int off = p*3 + qq;
                acc0 += w[off]*v0    + w[9+off]*p3  + w[18+off]*p5;
                acc1 += w[27+off]*v0 + w[36+off]*p3 + w[45+off]*p5;
            }
        }
        int i = i0 + oi;
        g_conv2[((m*2+0)*C2H + i)*C2W + j] = acc0;
        g_conv2[((m*2+1)*C2H + i)*C2W + j] = acc1;
        s0 += acc0; q0 += acc0*acc0;
        s1 += acc1; q1 += acc1*acc1;
    }
    blockRedAdd2(s0, q0, &g_s2[0], &g_q2[0]);
    blockRedAdd2(s1, q1, &g_s2[1], &g_q2[1]);
}

// conv3: slab-tiled. Block = (image m, half h). Coalesced slab load + smem FMA.
__global__ void __launch_bounds__(256) k_conv3(const float* __restrict__ w3,
                                               const float* __restrict__ b3,
                                               const float* __restrict__ g2,
                                               const float* __restrict__ be2){
    __shared__ float s_act[2][C3INMAX][C2W];   // 2*171*15*4 = 20520 B
    __shared__ float s_ab[4];

    int m  = blockIdx.x >> 1;
    int h  = blockIdx.x & 1;
    int i0 = h*C3HALF;
    int i1 = min(C3H, i0 + C3HALF);
    int r0 = 3*i0;
    int nr = 3*(i1 - i0);
    int tid = threadIdx.x;

    if (tid < 2){
        int c = tid;
        double mn = g_s2[c] / (double)N2;
        double vr = g_q2[c] / (double)N2 - mn*mn;
        double sc = (double)g2[c] / sqrt(vr + 1e-5);
        s_ab[c]   = (float)sc;
        s_ab[2+c] = (float)((double)be2[c] - mn*sc);
    }
    __syncthreads();

#pragma unroll
    for (int ch = 0; ch < 2; ch++){
        float A2 = s_ab[ch], B2 = s_ab[2+ch];
        const float* src = g_conv2 + ((size_t)(m*2+ch)*C2H + r0)*C2W;
        for (int idx = tid; idx < nr*C2W; idx += 256)
            s_act[ch][idx/C2W][idx%C2W] = lrelu(src[idx]*A2 + B2);
    }
    __syncthreads();

    float w[12];
#pragma unroll
    for (int p = 0; p < 12; p++) w[p] = __ldg(&w3[p]);
    float bb = __ldg(&b3[0]);

    float s = 0.f, q = 0.f;
    for (int o = tid; o < (i1-i0)*C3W; o += 256){
        int di = o / C3W, j = o % C3W;
        float acc = bb;
#pragma unroll
        for (int ch = 0; ch < 2; ch++)
#pragma unroll
            for (int p = 0; p < 3; p++)
#pragma unroll
                for (int qq = 0; qq < 2; qq++)
                    acc += w[ch*6 + p*2 + qq]*s_act[ch][3*di+p][2*j+qq];
        g_conv3[((size_t)m*C3H + i0 + di)*C3W + j] = acc;
        s += acc; q += acc*acc;
    }
    blockRedAdd2(s, q, &g_s3, &g_q3);
}

// fused rowval + genr + vint: 4 blocks per image (quarter of genr rows each)
__global__ void __launch_bounds__(256) k_mid(const float* __restrict__ cv,
                                             const float* __restrict__ VMM,
                                             const float* __restrict__ g3,
                                             const float* __restrict__ be3){
    __shared__ float s_rv[C3H];
    __shared__ float s_ab[2];
    int m   = blockIdx.x >> 2;
    int qtr = blockIdx.x & 3;
    int tid = threadIdx.x;

    if (tid == 0){
        double mn = g_s3 / (double)N3;
        double vr = g_q3 / (double)N3 - mn*mn;
        double sc = (double)g3[0] / sqrt(vr + 1e-5);
        s_ab[0] = (float)sc;
        s_ab[1] = (float)((double)be3[0] - mn*sc);
    }
    __syncthreads();
    float A3 = s_ab[0], B3 = s_ab[1];

    if (tid < C3H){
        const float wcol[7] = {4.f/37.f, 5.f/37.f, 6.f/37.f, 7.f/37.f, 6.f/37.f, 5.f/37.f, 4.f/37.f};
        const float* B = g_conv3 + (m*C3H + tid)*C3W;
        float rv = 0.f;
#pragma unroll
        for (int j = 0; j < 7; j++)
            rv += wcol[j] * lrelu(B[j]*A3 + B3);
        s_rv[tid] = rv;
    }

    if (qtr == 0){
        int b = m / KPS;
        const float* C = cv + m*NPK*2;
        const float dt = 7000.0f/255.0f;
        float vm0 = VMM[b*2];
        float dv = (VMM[b*2+1] - vm0)/255.0f;
        float tq = (float)tid;
        float tp = C[0]/dt, vp = (C[1] - vm0)/dv;
        float val;
        if (tq <= tp){
            val = vp;
        } else {
            val = (C[2*(NPK-1)+1] - vm0)/dv;
            for (int n = 1; n < NPK; n++){
                float tn = C[2*n]/dt, vn = (C[2*n+1] - vm0)/dv;
                if (tq <= tn){ val = vp + (vn - vp)*(tq - tp)/(tn - tp); break; }
                tp = tn; vp = vn;
            }
        }
        int vi = (int)val;
        g_vint[m*HHH + tid] = min(WCC-1, max(0, vi));
    }
    __syncthreads();

    int rh = qtr*256 + tid;
    float ih = (rh + 0.5f)*(113.0f/1024.0f) - 0.5f;
    ih = fminf(fmaxf(ih, 0.f), 112.f);
    int h0 = (int)ih; float f = ih - (float)h0;
    int h1 = min(h0 + 1, 112);
    g_genr[m*RHH + rh] = (1.f - f)*s_rv[h0] + f*s_rv[h1];
}

// sparse scatter of one source column v with weight w into mix row r
__device__ __forceinline__ void scatter_src(float* row, int v, float w){
    if (w == 0.f) return;
    if (v == 0){
        atomicAdd(&row[0], w);
        atomicAdd(&row[1], 0.75f*w);
        atomicAdd(&row[2], 0.25f*w);
    } else if (v == 255){
        atomicAdd(&row[509], 0.25f*w);
        atomicAdd(&row[510], 0.75f*w);
        atomicAdd(&row[511], w);
    } else {
        atomicAdd(&row[2*v-1], 0.25f*w);
        atomicAdd(&row[2*v  ], 0.75f*w);
        atomicAdd(&row[2*v+1], 0.75f*w);
        atomicAdd(&row[2*v+2], 0.25f*w);
    }
}

// fused mix (sparse) + conv_f: compute raw y, store it, accumulate stats
__global__ void __launch_bounds__(256) k_statsF(const float* __restrict__ wf,
                                                const float* __restrict__ bf){
    __shared__ float s_mix[TROWS+2][RWW];
    __shared__ float s_g[TROWS+2][8];
    __shared__ float s_w0[TROWS+2][8];
    __shared__ float s_w1[TROWS+2][8];
    __shared__ int   s_v0[TROWS+2][8];
    __shared__ int   s_v1[TROWS+2][8];
    __shared__ float s_base[TROWS+2];

    int b   = blockIdx.x / (RHH/TROWS);
    int rh0 = (blockIdx.x % (RHH/TROWS)) * TROWS;
    int tid = threadIdx.x;

    if (tid < (TROWS+2)*8){
        int r = tid >> 3, k = tid & 7;
        int gr = rh0 - 1 + r;
        float g = 0.f, fh = 0.f; int v0 = 0, v1 = 0;
        if (gr >= 0 && gr < RHH){
            float ih = (gr + 0.5f)*0.25f - 0.5f;
            ih = fminf(fmaxf(ih, 0.f), 255.f);
            int h0 = (int)ih; fh = ih - (float)h0; int h1 = min(h0 + 1, 255);
            int m = b*KPS + k;
            g  = g_genr[m*RHH + gr];
            v0 = g_vint[m*HHH + h0];
            v1 = g_vint[m*HHH + h1];
        }
        s_g[r][k] = g;
        s_w0[r][k] = 0.9f*g*(1.f - fh);
        s_w1[r][k] = 0.9f*g*fh;
        s_v0[r][k] = v0; s_v1[r][k] = v1;
    }
    __syncthreads();

    if (tid < TROWS+2){
        float s = 0.f;
#pragma unroll
        for (int k = 0; k < 8; k++) s += s_g[tid][k];
        s_base[tid] = 0.01f*s;
    }
    __syncthreads();

    // base fill
    for (int idx = tid; idx < (TROWS+2)*RWW; idx += 256){
        int r = idx >> 9, c = idx & 511;
        s_mix[r][c] = s_base[r];
    }
    __syncthreads();

    // sparse scatter
    if (tid < (TROWS+2)*8){
        int r = tid >> 3, k = tid & 7;
        scatter_src(&s_mix[r][0], s_v0[r][k], s_w0[r][k]);
        scatter_src(&s_mix[r][0], s_v1[r][k], s_w1[r][k]);
    }
    __syncthreads();

    float W[9];
#pragma unroll
    for (int i = 0; i < 9; i++) W[i] = __ldg(&wf[i]);
    float bb = __ldg(&bf[0]);

    float s = 0.f, q = 0.f;
    for (int orow = 0; orow < TROWS; orow++){
#pragma unroll
        for (int half = 0; half < 2; half++){
            int c = tid + half*256;
            float acc = bb;
#pragma unroll
            for (int p = 0; p < 3; p++){
#pragma unroll
                for (int qq = 0; qq < 3; qq++){
                    int cc = c - 1 + qq;
                    if (cc >= 0 && cc < RWW)
                        acc += W[p*3+qq]*s_mix[orow+p][cc];
                }
            }
            g_yraw[((size_t)b*RHH + rh0 + orow)*RWW + c] = acc;
            s += acc; q += acc*acc;
        }
    }
    blockRedAdd2(s, q, &g_sf, &g_qf);
}

// elementwise: out = lrelu(yraw*sc + sh), float4
__global__ void __launch_bounds__(256) k_final(const float* __restrict__ gf,
                                               const float* __restrict__ bef,
                                               float* __restrict__ out){
    __shared__ float s_ab[2];
    if (threadIdx.x == 0){
        double mn = g_sf / (double)NF;
        double vr = g_qf / (double)NF - mn*mn;
        double sc = (double)gf[0] / sqrt(vr + 1e-5);
        s_ab[0] = (float)sc;
        s_ab[1] = (float)((double)bef[0] - mn*sc);
    }
    __syncthreads();
    float sc = s_ab[0], sh = s_ab[1];

    int i = blockIdx.x*blockDim.x + threadIdx.x;
    if (i < NF/4){
        float4 y = ((const float4*)g_yraw)[i];
        float4 o;
        o.x = lrelu(y.x*sc + sh);
        o.y = lrelu(y.y*sc + sh);
        o.z = lrelu(y.z*sc + sh);
        o.w = lrelu(y.w*sc + sh);
        ((float4*)out)[i] = o;
    }
}

// ---------------- launch ----------------
extern "C" void kernel_launch(void* const* d_in, const int* in_sizes, int n_in,
                              void* d_out, int out_size){
    const float* gather = (const float*)d_in[0];
    const float* cv     = (const float*)d_in[1];
    const float* VMM    = (const float*)d_in[2];
    const float* w1  = (const float*)d_in[3];
    const float* g1  = (const float*)d_in[5];
    const float* be1 = (const float*)d_in[6];
    const float* w2  = (const float*)d_in[7];
    const float* b2  = (const float*)d_in[8];
    const float* g2  = (const float*)d_in[9];
    const float* be2 = (const float*)d_in[10];
    const float* w3  = (const float*)d_in[11];
    const float* b3  = (const float*)d_in[12];
    const float* g3  = (const float*)d_in[13];
    const float* be3 = (const float*)d_in[14];
    const float* wf  = (const float*)d_in[15];
    const float* bf  = (const float*)d_in[16];
    const float* gf  = (const float*)d_in[17];
    const float* bef = (const float*)d_in[18];
    float* out = (float*)d_out;

    k_init<<<1, 1>>>();
    k_conv1<<<MM*NS1, 256>>>(gather, w1);
    k_conv2<<<MM*NS2, 256>>>(w2, b2, g1, be1);
    k_conv3<<<MM*2, 256>>>(w3, b3, g2, be2);
    k_mid<<<MM*4, 256>>>(cv, VMM, g3, be3);
    k_statsF<<<BSZ*(RHH/TROWS), 256>>>(wf, bf);
    k_final<<<NF/4/256, 256>>>(gf, bef, out);
}